// round 13
// baseline (speedup 1.0000x reference)
#include <cuda_runtime.h>
#include <cuda_fp16.h>
#include <stdint.h>
#include <math.h>

// ---------------------------------------------------------------------------
// Problem constants
// ---------------------------------------------------------------------------
constexpr int B     = 32;
constexpr int NV    = 1556;
constexpr int NI    = 256;
constexpr int NT    = NV + NI;       // 1812
constexpr int D     = 512;
constexpr int IMGD  = 2048;

constexpr int M_IMG = B * NI;        // 8192  = 64*128
constexpr int M_Q   = B * NT;        // 57984 = 453*128
constexpr int M_K   = B * NV;        // 49792 = 389*128

constexpr float ATTN_SCALE = 0.08838834764831845f;  // (D/4)^-0.5

// weight split offsets (elements) in the packed weight buffers
constexpr long long OFF_FC = 0;
constexpr long long OFF_QW = (long long)D * IMGD;
constexpr long long OFF_KW = OFF_QW + (long long)D * D;
constexpr long long OFF_PW = OFF_KW + (long long)D * D;
constexpr long long OFF_FW = OFF_PW + (long long)D * D;
constexpr long long W_TOTAL = OFF_FW + (long long)D * D;

// ---------------------------------------------------------------------------
// Scratch (device globals; runtime allocation is forbidden)
// ---------------------------------------------------------------------------
__device__ __half g_xhi[(size_t)M_Q * D];
__device__ __half g_xlo[(size_t)M_Q * D];
__device__ __half g_ihi[(size_t)M_IMG * IMGD];
__device__ __half g_ilo[(size_t)M_IMG * IMGD];
__device__ float  g_q  [(size_t)M_Q * D];
__device__ float  g_k  [(size_t)M_K * D];
__device__ __half g_gkhi[(size_t)M_K * D];
__device__ __half g_gklo[(size_t)M_K * D];
__device__ __half g_thi[(size_t)M_K * D];
__device__ __half g_tlo[(size_t)M_K * D];
__device__ __half g_whi[(size_t)W_TOTAL];
__device__ __half g_wlo[(size_t)W_TOTAL];
__device__ float g_logit[(size_t)B * NT];
__device__ float g_stats[2 * B];
__device__ float g_gq   [(size_t)B * D];

// ---------------------------------------------------------------------------
// PTX helpers (ALL baseline sm_80-class: valid under compute_103 / sm_103)
// ---------------------------------------------------------------------------
__device__ __forceinline__ uint32_t smem_u32(const void* p) {
    uint32_t a;
    asm("{ .reg .u64 t; cvta.to.shared.u64 t, %1; cvt.u32.u64 %0, t; }"
        : "=r"(a) : "l"(p));
    return a;
}

#define CP_ASYNC16(dst, src) \
    asm volatile("cp.async.cg.shared.global [%0], [%1], 16;" \
                 :: "r"(dst), "l"(src) : "memory")
#define CP_COMMIT() asm volatile("cp.async.commit_group;" ::: "memory")
#define CP_WAIT(n)  asm volatile("cp.async.wait_group %0;" :: "n"(n) : "memory")

#define LDSM4(r0, r1, r2, r3, addr) \
    asm volatile("ldmatrix.sync.aligned.m8n8.x4.shared.b16 {%0,%1,%2,%3}, [%4];" \
                 : "=r"(r0), "=r"(r1), "=r"(r2), "=r"(r3) : "r"(addr))

// fp16 inputs, fp32 accumulate (main term)
#define MMA16816_F32(c, a, b0, b1) \
    asm volatile("mma.sync.aligned.m16n8k16.row.col.f32.f16.f16.f32 " \
                 "{%0,%1,%2,%3},{%4,%5,%6,%7},{%8,%9},{%0,%1,%2,%3};" \
                 : "+f"((c)[0]), "+f"((c)[1]), "+f"((c)[2]), "+f"((c)[3]) \
                 : "r"((a)[0]), "r"((a)[1]), "r"((a)[2]), "r"((a)[3]), \
                   "r"(b0), "r"(b1))

// fp16 inputs, fp16 accumulate (correction terms; C/D = 2 packed b32 regs)
#define MMA16816_F16(c, a, b0, b1) \
    asm volatile("mma.sync.aligned.m16n8k16.row.col.f16.f16.f16.f16 " \
                 "{%0,%1},{%2,%3,%4,%5},{%6,%7},{%0,%1};" \
                 : "+r"((c)[0]), "+r"((c)[1]) \
                 : "r"((a)[0]), "r"((a)[1]), "r"((a)[2]), "r"((a)[3]), \
                   "r"(b0), "r"(b1))

// ---------------------------------------------------------------------------
// fp16 split helpers
// ---------------------------------------------------------------------------
__device__ __forceinline__ uint32_t pkh(__half a, __half b) {
    __half2 t; t.x = a; t.y = b;
    return *reinterpret_cast<uint32_t*>(&t);
}
__device__ __forceinline__ void split2(float x, float y, uint32_t& h, uint32_t& l) {
    __half hx = __float2half(x), hy = __float2half(y);
    __half lx = __float2half(x - __half2float(hx));
    __half ly = __float2half(y - __half2float(hy));
    h = pkh(hx, hy); l = pkh(lx, ly);
}
__device__ __forceinline__ void split4(const float4 v, uint2& h, uint2& l) {
    split2(v.x, v.y, h.x, l.x);
    split2(v.z, v.w, h.y, l.y);
}

// ---------------------------------------------------------------------------
// Tensor-core GEMM (mma.sync fp16, split: hi*hi in f32 acc, hi*lo+lo*hi in
// one shared f16 acc):  C[r][0..511] = A[r][:] @ W^T  (+bias, +aux)
// A hi/lo with row remap: row R -> (R/rpbA)*strideA + (R%rpbA)*K (elements)
// W is [512][K] fp16 hi/lo row-major. grid = (M/128, 4), 256 threads.
// Output fp32 (outF) or re-split fp16 (outHi/outLo), row remap rpbO/strideO.
// 2 stages x 40KB smem -> 2 CTAs/SM.
// ---------------------------------------------------------------------------
constexpr int ROWB    = 80;                 // padded row stride (32 fp16 + 16B pad)
constexpr int TILEB   = 128 * ROWB;         // 10240 B per operand tile
constexpr int STAGEB  = 4 * TILEB;          // Ahi,Alo,Bhi,Blo = 40960 B
constexpr int NSTAGE  = 2;
constexpr int SMEM_GEMM = NSTAGE * STAGEB;  // 81920 B

__global__ __launch_bounds__(256, 2)
void mma_gemm(const __half* __restrict__ Ahi,
              const __half* __restrict__ Alo,
              int K, int rpbA, long long strideA,
              const __half* __restrict__ Whi,
              const __half* __restrict__ Wlo,
              const float* __restrict__ bias,
              const float* __restrict__ aux, int rpbX, long long strideX,
              float* __restrict__ outF,
              __half* __restrict__ outHi, __half* __restrict__ outLo,
              int rpbO, long long strideO)
{
    extern __shared__ char smem[];
    const uint32_t sbase = smem_u32(smem);

    const int tid  = threadIdx.x;
    const int wid  = tid >> 5;
    const int lane = tid & 31;
    const int bm   = blockIdx.x, bn = blockIdx.y;
    const int wm   = wid >> 2;          // 0..1  (m 64-row half)
    const int wn   = wid & 3;           // 0..3  (n 32-col quarter)

    // ---- global-load indexing: thread t -> tile row t/2, 16B units (t&1)*2,+1
    const int lr = tid >> 1;            // 0..127
    const int lu = (tid & 1) * 2;       // 0 or 2
    const int aRow = bm * 128 + lr;
    const char* aHiP = (const char*)(Ahi + (long long)(aRow / rpbA) * strideA +
                                           (long long)(aRow % rpbA) * K);
    const char* aLoP = (const char*)(Alo + (long long)(aRow / rpbA) * strideA +
                                           (long long)(aRow % rpbA) * K);
    const char* bHiP = (const char*)(Whi + (long long)(bn * 128 + lr) * K);
    const char* bLoP = (const char*)(Wlo + (long long)(bn * 128 + lr) * K);
    const uint32_t dRow = sbase + (uint32_t)lr * ROWB + (uint32_t)lu * 16;

    auto stage_load = [&](int c, int stg) {
        const uint32_t sd = dRow + (uint32_t)stg * STAGEB;
        const long long go = (long long)c * 64 + lu * 16;
        CP_ASYNC16(sd + 0 * TILEB +  0, aHiP + go);
        CP_ASYNC16(sd + 0 * TILEB + 16, aHiP + go + 16);
        CP_ASYNC16(sd + 1 * TILEB +  0, aLoP + go);
        CP_ASYNC16(sd + 1 * TILEB + 16, aLoP + go + 16);
        CP_ASYNC16(sd + 2 * TILEB +  0, bHiP + go);
        CP_ASYNC16(sd + 2 * TILEB + 16, bHiP + go + 16);
        CP_ASYNC16(sd + 3 * TILEB +  0, bLoP + go);
        CP_ASYNC16(sd + 3 * TILEB + 16, bLoP + go + 16);
    };

    // ---- ldmatrix address components (per warp/lane) ----
    const uint32_t aOffBase = (uint32_t)(wm * 64 + (lane & 15)) * ROWB +
                              (uint32_t)(lane >> 4) * 16;
    const int brow0   = wn * 32 + (lane & 7) + ((lane >> 4) << 3);
    const uint32_t bColOff = (uint32_t)((lane >> 3) & 1) * 16;

    float acc[4][4][4];          // main term, fp32 accumulate
    uint32_t accX[4][4][2];      // cross terms, fp16 accumulate (packed)
#pragma unroll
    for (int i = 0; i < 4; i++)
#pragma unroll
        for (int j = 0; j < 4; j++) {
#pragma unroll
            for (int r = 0; r < 4; r++) acc[i][j][r] = 0.f;
            accX[i][j][0] = 0u; accX[i][j][1] = 0u;
        }

    const int nk = K / 32;

    // prologue: stage 0 in flight (R9 ordering)
    stage_load(0, 0);
    CP_COMMIT();

    for (int c = 0; c < nk; c++) {
        CP_WAIT(0);
        __syncthreads();
        if (c + 1 < nk) stage_load(c + 1, (c + 1) & 1);
        CP_COMMIT();

        const uint32_t sb = sbase + (uint32_t)(c & 1) * STAGEB;
#pragma unroll
        for (int s = 0; s < 2; s++) {               // two k16 steps per chunk
            // B fragments for this k-step (held across the i loop)
            uint32_t bH[4][2], bL[4][2];
#pragma unroll
            for (int jp = 0; jp < 2; jp++) {
                const uint32_t ba = sb + 2 * TILEB +
                                    (uint32_t)(brow0 + jp * 16) * ROWB +
                                    bColOff + s * 32;
                LDSM4(bH[2 * jp][0], bH[2 * jp][1], bH[2 * jp + 1][0], bH[2 * jp + 1][1], ba);
                LDSM4(bL[2 * jp][0], bL[2 * jp][1], bL[2 * jp + 1][0], bL[2 * jp + 1][1], ba + TILEB);
            }
            // A fragments loaded just-in-time per m-subtile (short live range)
#pragma unroll
            for (int i = 0; i < 4; i++) {
                uint32_t aH[4], aL[4];
                const uint32_t aa = sb + aOffBase + (uint32_t)i * (16 * ROWB) + s * 32;
                LDSM4(aH[0], aH[1], aH[2], aH[3], aa);
                LDSM4(aL[0], aL[1], aL[2], aL[3], aa + TILEB);
#pragma unroll
                for (int j = 0; j < 4; j++) {
                    MMA16816_F32(acc[i][j], aH, bH[j][0], bH[j][1]);
                    MMA16816_F16(accX[i][j], aH, bL[j][0], bL[j][1]);
                    MMA16816_F16(accX[i][j], aL, bH[j][0], bH[j][1]);
                }
            }
        }
        __syncthreads();
    }

    // ---- epilogue ----
    const int l4 = lane >> 2;
    const int l2 = (lane & 3) * 2;
#pragma unroll
    for (int i = 0; i < 4; i++) {
#pragma unroll
        for (int h = 0; h < 2; h++) {
            const int R = bm * 128 + wm * 64 + i * 16 + l4 + h * 8;
            const long long oBase = (long long)(R / rpbO) * strideO +
                                    (long long)(R % rpbO) * 512;
            long long xBase = 0;
            if (aux) xBase = (long long)(R / rpbX) * strideX +
                             (long long)(R % rpbX) * 512;
#pragma unroll
            for (int j = 0; j < 4; j++) {
                const int cb = bn * 128 + wn * 32 + j * 8 + l2;
                const float2 cx = __half22float2(
                    *reinterpret_cast<const __half2*>(&accX[i][j][h]));
                float vx = acc[i][j][h * 2 + 0] + cx.x;
                float vy = acc[i][j][h * 2 + 1] + cx.y;
                const float2 bb = *(const float2*)(bias + cb);
                vx += bb.x; vy += bb.y;
                if (aux) {
                    const float2 ax = *(const float2*)(aux + xBase + cb);
                    vx += ax.x; vy += ax.y;
                }
                if (outF) {
                    float2 o; o.x = vx; o.y = vy;
                    *(float2*)(outF + oBase + cb) = o;
                } else {
                    uint32_t hh, ll;
                    split2(vx, vy, hh, ll);
                    *(uint32_t*)(outHi + oBase + cb) = hh;
                    *(uint32_t*)(outLo + oBase + cb) = ll;
                }
            }
        }
    }
}

// ---------------------------------------------------------------------------
// Elementwise / split / reduction kernels
// ---------------------------------------------------------------------------

// fused split of fc_w, q_w, k_w, proj_w into the packed whi/wlo buffers
__global__ void split_w4_kernel(const float4* __restrict__ fc,
                                const float4* __restrict__ qw,
                                const float4* __restrict__ kw,
                                const float4* __restrict__ pw,
                                uint2* __restrict__ hi, uint2* __restrict__ lo)
{
    long long i = (long long)blockIdx.x * blockDim.x + threadIdx.x;  // float4 idx
    const long long e_fc = OFF_QW / 4, e_qw = OFF_KW / 4,
                    e_kw = OFF_PW / 4, e_pw = OFF_FW / 4;
    if (i >= e_pw) return;
    float4 v;
    if (i < e_fc)       v = fc[i];
    else if (i < e_qw)  v = qw[i - e_fc];
    else if (i < e_kw)  v = kw[i - e_qw];
    else                v = pw[i - e_kw];
    uint2 h, l;
    split4(v, h, l);
    hi[i] = h; lo[i] = l;
}

__global__ void split_kernel(const float4* __restrict__ src,
                             uint2* __restrict__ hi, uint2* __restrict__ lo,
                             long long n4)
{
    long long i = (long long)blockIdx.x * blockDim.x + threadIdx.x;
    if (i >= n4) return;
    uint2 h, l;
    split4(src[i], h, l);
    hi[i] = h; lo[i] = l;
}

__global__ void split_verts_kernel(const float4* __restrict__ src,
                                   uint2* __restrict__ xhi, uint2* __restrict__ xlo)
{
    long long idx = (long long)blockIdx.x * blockDim.x + threadIdx.x;
    const long long total = (long long)M_K * (D / 4);
    if (idx >= total) return;
    const int c = (int)(idx & 127);
    const long long r = idx >> 7;
    const int b = (int)(r / NV), n = (int)(r % NV);
    const long long dst = ((long long)b * NT + n) * 128 + c;
    uint2 h, l;
    split4(src[idx], h, l);
    xhi[dst] = h; xlo[dst] = l;
}

__global__ void l2norm_kernel(float* __restrict__ Q, int M,
                              const float* __restrict__ wg,
                              float* __restrict__ logit)
{
    const int gw   = (int)(((long long)blockIdx.x * blockDim.x + threadIdx.x) >> 5);
    const int lane = threadIdx.x & 31;
    if (gw >= M) return;
    float4* row = (float4*)(Q + (long long)gw * D);
    float4 v[4];
    float ss = 0.f, dg = 0.f;
#pragma unroll
    for (int i = 0; i < 4; i++) {
        v[i] = row[lane + 32 * i];
        ss += v[i].x * v[i].x + v[i].y * v[i].y + v[i].z * v[i].z + v[i].w * v[i].w;
    }
    if (wg) {
#pragma unroll
        for (int i = 0; i < 4; i++) {
            float4 w = ((const float4*)wg)[lane + 32 * i];
            dg += v[i].x * w.x + v[i].y * w.y + v[i].z * w.z + v[i].w * w.w;
        }
    }
#pragma unroll
    for (int o = 16; o > 0; o >>= 1) {
        ss += __shfl_xor_sync(0xffffffffu, ss, o);
        dg += __shfl_xor_sync(0xffffffffu, dg, o);
    }
    const float inv = 1.f / fmaxf(sqrtf(ss), 1e-12f);
#pragma unroll
    for (int i = 0; i < 4; i++) {
        v[i].x *= inv; v[i].y *= inv; v[i].z *= inv; v[i].w *= inv;
        row[lane + 32 * i] = v[i];
    }
    if (wg && lane == 0) logit[gw] = dg * inv * ATTN_SCALE;
}

__global__ void softmax_stats_kernel(const float* __restrict__ logit,
                                     float* __restrict__ stats)
{
    const int b = blockIdx.x;
    const int tid = threadIdx.x;
    __shared__ float red[256];
    float mx = -1e30f;
    for (int n = tid; n < NT; n += 256) mx = fmaxf(mx, logit[b * NT + n]);
    red[tid] = mx; __syncthreads();
    for (int s = 128; s > 0; s >>= 1) {
        if (tid < s) red[tid] = fmaxf(red[tid], red[tid + s]);
        __syncthreads();
    }
    const float m = red[0]; __syncthreads();
    float se = 0.f;
    for (int n = tid; n < NT; n += 256) se += expf(logit[b * NT + n] - m);
    red[tid] = se; __syncthreads();
    for (int s = 128; s > 0; s >>= 1) {
        if (tid < s) red[tid] += red[tid + s];
        __syncthreads();
    }
    if (tid == 0) { stats[2 * b] = m; stats[2 * b + 1] = red[0]; }
}

__global__ void compute_g_kernel(const float* __restrict__ q,
                                 const float* __restrict__ logit,
                                 const float* __restrict__ stats,
                                 float* __restrict__ g)
{
    const int b = blockIdx.x;
    const int d = blockIdx.y * 128 + threadIdx.x;
    const float m = stats[2 * b];
    const float inv_s = 1.f / stats[2 * b + 1];
    __shared__ float w[128];
    float acc = 0.f;
    const float* qb = q + (long long)b * NT * D;
    for (int n0 = 0; n0 < NT; n0 += 128) {
        const int n = n0 + threadIdx.x;
        w[threadIdx.x] = (n < NT) ? expf(logit[b * NT + n] - m) * inv_s : 0.f;
        __syncthreads();
        const int lim = min(128, NT - n0);
        for (int j = 0; j < lim; j++)
            acc += w[j] * qb[(long long)(n0 + j) * D + d];
        __syncthreads();
    }
    g[b * D + d] = acc;
}

__global__ void scale_split_k_kernel(const float4* __restrict__ k,
                                     const float4* __restrict__ g,
                                     uint2* __restrict__ hi, uint2* __restrict__ lo)
{
    long long idx = (long long)blockIdx.x * blockDim.x + threadIdx.x;
    const long long total = (long long)M_K * (D / 4);
    if (idx >= total) return;
    const int c = (int)(idx & 127);
    const int b = (int)((idx >> 7) / NV);
    float4 kv = k[idx];
    const float4 gv = g[b * 128 + c];
    kv.x *= gv.x; kv.y *= gv.y; kv.z *= gv.z; kv.w *= gv.w;
    uint2 h, l;
    split4(kv, h, l);
    hi[idx] = h; lo[idx] = l;
}

// ---------------------------------------------------------------------------
// launch
// ---------------------------------------------------------------------------
extern "C" void kernel_launch(void* const* d_in, const int* in_sizes, int n_in,
                              void* d_out, int out_size)
{
    (void)in_sizes; (void)n_in; (void)out_size;

    const float* verts_f = (const float*)d_in[0];
    const float* img_f   = (const float*)d_in[1];
    const float* fc_w    = (const float*)d_in[2];
    const float* fc_b    = (const float*)d_in[3];
    const float* q_w     = (const float*)d_in[4];
    const float* q_b     = (const float*)d_in[5];
    const float* k_w     = (const float*)d_in[6];
    const float* k_b     = (const float*)d_in[7];
    const float* w_g     = (const float*)d_in[8];
    const float* proj_w  = (const float*)d_in[9];
    const float* proj_b  = (const float*)d_in[10];
    const float* final_w = (const float*)d_in[11];
    const float* final_b = (const float*)d_in[12];
    float* out = (float*)d_out;

    __half *xhi, *xlo, *ihi, *ilo, *gkhi, *gklo, *thi, *tlo, *whi, *wlo;
    float *q, *k, *logit, *stats, *gq;
    cudaGetSymbolAddress((void**)&xhi,  g_xhi);
    cudaGetSymbolAddress((void**)&xlo,  g_xlo);
    cudaGetSymbolAddress((void**)&ihi,  g_ihi);
    cudaGetSymbolAddress((void**)&ilo,  g_ilo);
    cudaGetSymbolAddress((void**)&gkhi, g_gkhi);
    cudaGetSymbolAddress((void**)&gklo, g_gklo);
    cudaGetSymbolAddress((void**)&thi,  g_thi);
    cudaGetSymbolAddress((void**)&tlo,  g_tlo);
    cudaGetSymbolAddress((void**)&whi,  g_whi);
    cudaGetSymbolAddress((void**)&wlo,  g_wlo);
    cudaGetSymbolAddress((void**)&q,     g_q);
    cudaGetSymbolAddress((void**)&k,     g_k);
    cudaGetSymbolAddress((void**)&logit, g_logit);
    cudaGetSymbolAddress((void**)&stats, g_stats);
    cudaGetSymbolAddress((void**)&gq,    g_gq);

    cudaFuncSetAttribute(mma_gemm, cudaFuncAttributeMaxDynamicSharedMemorySize,
                         SMEM_GEMM);

    const long long sNT = (long long)NT * D;
    const long long ewT = (long long)M_K * (D / 4);
    const int ewB = (int)((ewT + 255) / 256);

    // --- input splits ---
    {
        const long long n4 = OFF_FW / 4;
        split_w4_kernel<<<(int)((n4 + 255) / 256), 256>>>(
            (const float4*)fc_w, (const float4*)q_w,
            (const float4*)k_w, (const float4*)proj_w,
            (uint2*)whi, (uint2*)wlo);
    }
    {
        const long long n4 = (long long)D * D / 4;
        split_kernel<<<(int)((n4 + 255) / 256), 256>>>(
            (const float4*)final_w, (uint2*)(whi + OFF_FW), (uint2*)(wlo + OFF_FW), n4);
    }
    {
        const long long n4 = (long long)M_IMG * IMGD / 4;
        split_kernel<<<(int)((n4 + 255) / 256), 256>>>(
            (const float4*)img_f, (uint2*)ihi, (uint2*)ilo, n4);
    }
    split_verts_kernel<<<ewB, 256>>>((const float4*)verts_f,
                                     (uint2*)xhi, (uint2*)xlo);

    // x[:, NV:] = img_f @ fc_w^T + fc_b  (split output into x hi/lo)
    mma_gemm<<<dim3(M_IMG / 128, 4), 256, SMEM_GEMM>>>(
        ihi, ilo, IMGD, M_IMG, 0LL,
        whi + OFF_FC, wlo + OFF_FC, fc_b,
        nullptr, 1, 0LL,
        nullptr, xhi + (long long)NV * D, xlo + (long long)NV * D,
        NI, sNT);

    // q = x @ q_w^T + q_b (all tokens, fp32 out)
    mma_gemm<<<dim3(M_Q / 128, 4), 256, SMEM_GEMM>>>(
        xhi, xlo, D, M_Q, 0LL,
        whi + OFF_QW, wlo + OFF_QW, q_b,
        nullptr, 1, 0LL,
        q, nullptr, nullptr, M_Q, 0LL);
    l2norm_kernel<<<(M_Q * 32 + 255) / 256, 256>>>(q, M_Q, w_g, logit);

    // k = x_vert @ k_w^T + k_b (vertex tokens, fp32 out)
    mma_gemm<<<dim3(M_K / 128, 4), 256, SMEM_GEMM>>>(
        xhi, xlo, D, NV, sNT,
        whi + OFF_KW, wlo + OFF_KW, k_b,
        nullptr, 1, 0LL,
        k, nullptr, nullptr, M_K, 0LL);
    l2norm_kernel<<<(M_K * 32 + 255) / 256, 256>>>(k, M_K, nullptr, nullptr);

    // softmax + global query
    softmax_stats_kernel<<<B, 256>>>(logit, stats);
    compute_g_kernel<<<dim3(B, 4), 128>>>(q, logit, stats, gq);

    // gk = g * k, split
    scale_split_k_kernel<<<ewB, 256>>>((const float4*)k, (const float4*)gq,
                                       (uint2*)gkhi, (uint2*)gklo);

    // t = gk @ proj_w^T + proj_b + q_vert (split output)
    mma_gemm<<<dim3(M_K / 128, 4), 256, SMEM_GEMM>>>(
        gkhi, gklo, D, M_K, 0LL,
        whi + OFF_PW, wlo + OFF_PW, proj_b,
        q, NV, sNT,
        nullptr, thi, tlo, M_K, 0LL);

    // out = t @ final_w^T + final_b + verts_f (fp32 out)
    mma_gemm<<<dim3(M_K / 128, 4), 256, SMEM_GEMM>>>(
        thi, tlo, D, M_K, 0LL,
        whi + OFF_FW, wlo + OFF_FW, final_b,
        verts_f, M_K, 0LL,
        out, nullptr, nullptr, M_K, 0LL);
}

// round 15
// speedup vs baseline: 1.3882x; 1.3882x over previous
#include <cuda_runtime.h>
#include <cuda_fp16.h>
#include <stdint.h>
#include <math.h>

// ---------------------------------------------------------------------------
// Problem constants
// ---------------------------------------------------------------------------
constexpr int B     = 32;
constexpr int NV    = 1556;
constexpr int NI    = 256;
constexpr int NT    = NV + NI;       // 1812
constexpr int D     = 512;
constexpr int IMGD  = 2048;

constexpr int M_IMG = B * NI;        // 8192  = 64*128
constexpr int M_Q   = B * NT;        // 57984 = 453*128
constexpr int M_K   = B * NV;        // 49792 = 389*128

constexpr float ATTN_SCALE = 0.08838834764831845f;  // (D/4)^-0.5

// weight offsets (elements) in the packed fp16 weight buffer (hi only)
constexpr long long OFF_FC = 0;
constexpr long long OFF_QW = (long long)D * IMGD;
constexpr long long OFF_KW = OFF_QW + (long long)D * D;
constexpr long long OFF_PW = OFF_KW + (long long)D * D;
constexpr long long OFF_FW = OFF_PW + (long long)D * D;
constexpr long long W_TOTAL = OFF_FW + (long long)D * D;

// ---------------------------------------------------------------------------
// Scratch (device globals; runtime allocation is forbidden)
// ---------------------------------------------------------------------------
__device__ __half g_xhi[(size_t)M_Q * D];
__device__ __half g_xlo[(size_t)M_Q * D];
__device__ __half g_ihi[(size_t)M_IMG * IMGD];
__device__ __half g_ilo[(size_t)M_IMG * IMGD];
__device__ float  g_q  [(size_t)M_Q * D];
__device__ float  g_k  [(size_t)M_K * D];
__device__ __half g_gkhi[(size_t)M_K * D];
__device__ __half g_gklo[(size_t)M_K * D];
__device__ __half g_thi[(size_t)M_K * D];
__device__ __half g_tlo[(size_t)M_K * D];
__device__ __half g_whi[(size_t)W_TOTAL];
__device__ float g_logit[(size_t)B * NT];
__device__ float g_stats[2 * B];
__device__ float g_gq   [(size_t)B * D];

// ---------------------------------------------------------------------------
// PTX helpers (ALL baseline sm_80-class: valid under compute_103 / sm_103)
// ---------------------------------------------------------------------------
__device__ __forceinline__ uint32_t smem_u32(const void* p) {
    uint32_t a;
    asm("{ .reg .u64 t; cvta.to.shared.u64 t, %1; cvt.u32.u64 %0, t; }"
        : "=r"(a) : "l"(p));
    return a;
}

#define CP_ASYNC16(dst, src) \
    asm volatile("cp.async.cg.shared.global [%0], [%1], 16;" \
                 :: "r"(dst), "l"(src) : "memory")
#define CP_COMMIT() asm volatile("cp.async.commit_group;" ::: "memory")
#define CP_WAIT(n)  asm volatile("cp.async.wait_group %0;" :: "n"(n) : "memory")

#define LDSM4(r0, r1, r2, r3, addr) \
    asm volatile("ldmatrix.sync.aligned.m8n8.x4.shared.b16 {%0,%1,%2,%3}, [%4];" \
                 : "=r"(r0), "=r"(r1), "=r"(r2), "=r"(r3) : "r"(addr))

// fp16 inputs, fp32 accumulate
#define MMA16816_F32(c, a, b0, b1) \
    asm volatile("mma.sync.aligned.m16n8k16.row.col.f32.f16.f16.f32 " \
                 "{%0,%1,%2,%3},{%4,%5,%6,%7},{%8,%9},{%0,%1,%2,%3};" \
                 : "+f"((c)[0]), "+f"((c)[1]), "+f"((c)[2]), "+f"((c)[3]) \
                 : "r"((a)[0]), "r"((a)[1]), "r"((a)[2]), "r"((a)[3]), \
                   "r"(b0), "r"(b1))

// ---------------------------------------------------------------------------
// fp16 split helpers
// ---------------------------------------------------------------------------
__device__ __forceinline__ uint32_t pkh(__half a, __half b) {
    __half2 t; t.x = a; t.y = b;
    return *reinterpret_cast<uint32_t*>(&t);
}
__device__ __forceinline__ void split2(float x, float y, uint32_t& h, uint32_t& l) {
    __half hx = __float2half(x), hy = __float2half(y);
    __half lx = __float2half(x - __half2float(hx));
    __half ly = __float2half(y - __half2float(hy));
    h = pkh(hx, hy); l = pkh(lx, ly);
}
__device__ __forceinline__ void split4(const float4 v, uint2& h, uint2& l) {
    split2(v.x, v.y, h.x, l.x);
    split2(v.z, v.w, h.y, l.y);
}
__device__ __forceinline__ uint2 cvt4(const float4 v) {
    uint2 h;
    h.x = pkh(__float2half(v.x), __float2half(v.y));
    h.y = pkh(__float2half(v.z), __float2half(v.w));
    return h;
}

// ---------------------------------------------------------------------------
// Tensor-core GEMM (mma.sync fp16, 2-term split: (Ahi+Alo)·Bhi, f32 acc):
//   C[r][0..511] = A[r][:] @ W^T  (+bias, +aux)
// A hi/lo with row remap: row R -> (R/rpbA)*strideA + (R%rpbA)*K (elements)
// W is [512][K] fp16 row-major (hi only). grid = (M/128, 4), 256 threads.
// Output fp32 (outF) or re-split fp16 (outHi/outLo), row remap rpbO/strideO.
// 2 stages x 30KB smem -> 2 CTAs/SM.
// ---------------------------------------------------------------------------
constexpr int ROWB    = 80;                 // padded row stride (32 fp16 + 16B pad)
constexpr int TILEB   = 128 * ROWB;         // 10240 B per operand tile
constexpr int STAGEB  = 3 * TILEB;          // Ahi,Alo,Bhi = 30720 B
constexpr int NSTAGE  = 2;
constexpr int SMEM_GEMM = NSTAGE * STAGEB;  // 61440 B

__global__ __launch_bounds__(256, 2)
void mma_gemm(const __half* __restrict__ Ahi,
              const __half* __restrict__ Alo,
              int K, int rpbA, long long strideA,
              const __half* __restrict__ Whi,
              const float* __restrict__ bias,
              const float* __restrict__ aux, int rpbX, long long strideX,
              float* __restrict__ outF,
              __half* __restrict__ outHi, __half* __restrict__ outLo,
              int rpbO, long long strideO)
{
    extern __shared__ char smem[];
    const uint32_t sbase = smem_u32(smem);

    const int tid  = threadIdx.x;
    const int wid  = tid >> 5;
    const int lane = tid & 31;
    const int bm   = blockIdx.x, bn = blockIdx.y;
    const int wm   = wid >> 2;          // 0..1  (m 64-row half)
    const int wn   = wid & 3;           // 0..3  (n 32-col quarter)

    // ---- global-load indexing: thread t -> tile row t/2, 16B units (t&1)*2,+1
    const int lr = tid >> 1;            // 0..127
    const int lu = (tid & 1) * 2;       // 0 or 2
    const int aRow = bm * 128 + lr;
    const char* aHiP = (const char*)(Ahi + (long long)(aRow / rpbA) * strideA +
                                           (long long)(aRow % rpbA) * K);
    const char* aLoP = (const char*)(Alo + (long long)(aRow / rpbA) * strideA +
                                           (long long)(aRow % rpbA) * K);
    const char* bHiP = (const char*)(Whi + (long long)(bn * 128 + lr) * K);
    const uint32_t dRow = sbase + (uint32_t)lr * ROWB + (uint32_t)lu * 16;

    auto stage_load = [&](int c, int stg) {
        const uint32_t sd = dRow + (uint32_t)stg * STAGEB;
        const long long go = (long long)c * 64 + lu * 16;
        CP_ASYNC16(sd + 0 * TILEB +  0, aHiP + go);
        CP_ASYNC16(sd + 0 * TILEB + 16, aHiP + go + 16);
        CP_ASYNC16(sd + 1 * TILEB +  0, aLoP + go);
        CP_ASYNC16(sd + 1 * TILEB + 16, aLoP + go + 16);
        CP_ASYNC16(sd + 2 * TILEB +  0, bHiP + go);
        CP_ASYNC16(sd + 2 * TILEB + 16, bHiP + go + 16);
    };

    // ---- ldmatrix address components (per warp/lane) ----
    const uint32_t aOffBase = (uint32_t)(wm * 64 + (lane & 15)) * ROWB +
                              (uint32_t)(lane >> 4) * 16;
    const int brow0   = wn * 32 + (lane & 7) + ((lane >> 4) << 3);
    const uint32_t bColOff = (uint32_t)((lane >> 3) & 1) * 16;

    float acc[4][4][4];
#pragma unroll
    for (int i = 0; i < 4; i++)
#pragma unroll
        for (int j = 0; j < 4; j++)
#pragma unroll
            for (int r = 0; r < 4; r++) acc[i][j][r] = 0.f;

    const int nk = K / 32;

    // prologue: stage 0 in flight
    stage_load(0, 0);
    CP_COMMIT();

    for (int c = 0; c < nk; c++) {
        CP_WAIT(0);
        __syncthreads();
        if (c + 1 < nk) stage_load(c + 1, (c + 1) & 1);
        CP_COMMIT();

        const uint32_t sb = sbase + (uint32_t)(c & 1) * STAGEB;
#pragma unroll
        for (int s = 0; s < 2; s++) {               // two k16 steps per chunk
            // B fragments for this k-step (weights, hi only)
            uint32_t bH[4][2];
#pragma unroll
            for (int jp = 0; jp < 2; jp++) {
                const uint32_t ba = sb + 2 * TILEB +
                                    (uint32_t)(brow0 + jp * 16) * ROWB +
                                    bColOff + s * 32;
                LDSM4(bH[2 * jp][0], bH[2 * jp][1], bH[2 * jp + 1][0], bH[2 * jp + 1][1], ba);
            }
            // A fragments loaded just-in-time per m-subtile
#pragma unroll
            for (int i = 0; i < 4; i++) {
                uint32_t aH[4], aL[4];
                const uint32_t aa = sb + aOffBase + (uint32_t)i * (16 * ROWB) + s * 32;
                LDSM4(aH[0], aH[1], aH[2], aH[3], aa);
                LDSM4(aL[0], aL[1], aL[2], aL[3], aa + TILEB);
#pragma unroll
                for (int j = 0; j < 4; j++) {
                    MMA16816_F32(acc[i][j], aH, bH[j][0], bH[j][1]);
                    MMA16816_F32(acc[i][j], aL, bH[j][0], bH[j][1]);
                }
            }
        }
        __syncthreads();
    }

    // ---- epilogue ----
    const int l4 = lane >> 2;
    const int l2 = (lane & 3) * 2;
#pragma unroll
    for (int i = 0; i < 4; i++) {
#pragma unroll
        for (int h = 0; h < 2; h++) {
            const int R = bm * 128 + wm * 64 + i * 16 + l4 + h * 8;
            const long long oBase = (long long)(R / rpbO) * strideO +
                                    (long long)(R % rpbO) * 512;
            long long xBase = 0;
            if (aux) xBase = (long long)(R / rpbX) * strideX +
                             (long long)(R % rpbX) * 512;
#pragma unroll
            for (int j = 0; j < 4; j++) {
                const int cb = bn * 128 + wn * 32 + j * 8 + l2;
                float vx = acc[i][j][h * 2 + 0];
                float vy = acc[i][j][h * 2 + 1];
                const float2 bb = *(const float2*)(bias + cb);
                vx += bb.x; vy += bb.y;
                if (aux) {
                    const float2 ax = *(const float2*)(aux + xBase + cb);
                    vx += ax.x; vy += ax.y;
                }
                if (outF) {
                    float2 o; o.x = vx; o.y = vy;
                    *(float2*)(outF + oBase + cb) = o;
                } else {
                    uint32_t hh, ll;
                    split2(vx, vy, hh, ll);
                    *(uint32_t*)(outHi + oBase + cb) = hh;
                    *(uint32_t*)(outLo + oBase + cb) = ll;
                }
            }
        }
    }
}

// ---------------------------------------------------------------------------
// Elementwise / split / reduction kernels
// ---------------------------------------------------------------------------

// fused fp32->fp16 convert (hi only) of all 5 weight matrices into g_whi
__global__ void convert_w_kernel(const float4* __restrict__ fc,
                                 const float4* __restrict__ qw,
                                 const float4* __restrict__ kw,
                                 const float4* __restrict__ pw,
                                 const float4* __restrict__ fw,
                                 uint2* __restrict__ hi)
{
    long long i = (long long)blockIdx.x * blockDim.x + threadIdx.x;  // float4 idx
    const long long e_fc = OFF_QW / 4, e_qw = OFF_KW / 4,
                    e_kw = OFF_PW / 4, e_pw = OFF_FW / 4,
                    e_fw = W_TOTAL / 4;
    if (i >= e_fw) return;
    float4 v;
    if (i < e_fc)       v = fc[i];
    else if (i < e_qw)  v = qw[i - e_fc];
    else if (i < e_kw)  v = kw[i - e_qw];
    else if (i < e_pw)  v = pw[i - e_kw];
    else                v = fw[i - e_pw];
    hi[i] = cvt4(v);
}

__global__ void split_kernel(const float4* __restrict__ src,
                             uint2* __restrict__ hi, uint2* __restrict__ lo,
                             long long n4)
{
    long long i = (long long)blockIdx.x * blockDim.x + threadIdx.x;
    if (i >= n4) return;
    uint2 h, l;
    split4(src[i], h, l);
    hi[i] = h; lo[i] = l;
}

__global__ void split_verts_kernel(const float4* __restrict__ src,
                                   uint2* __restrict__ xhi, uint2* __restrict__ xlo)
{
    long long idx = (long long)blockIdx.x * blockDim.x + threadIdx.x;
    const long long total = (long long)M_K * (D / 4);
    if (idx >= total) return;
    const int c = (int)(idx & 127);
    const long long r = idx >> 7;
    const int b = (int)(r / NV), n = (int)(r % NV);
    const long long dst = ((long long)b * NT + n) * 128 + c;
    uint2 h, l;
    split4(src[idx], h, l);
    xhi[dst] = h; xlo[dst] = l;
}

__global__ void l2norm_kernel(float* __restrict__ Q, int M,
                              const float* __restrict__ wg,
                              float* __restrict__ logit)
{
    const int gw   = (int)(((long long)blockIdx.x * blockDim.x + threadIdx.x) >> 5);
    const int lane = threadIdx.x & 31;
    if (gw >= M) return;
    float4* row = (float4*)(Q + (long long)gw * D);
    float4 v[4];
    float ss = 0.f, dg = 0.f;
#pragma unroll
    for (int i = 0; i < 4; i++) {
        v[i] = row[lane + 32 * i];
        ss += v[i].x * v[i].x + v[i].y * v[i].y + v[i].z * v[i].z + v[i].w * v[i].w;
    }
    if (wg) {
#pragma unroll
        for (int i = 0; i < 4; i++) {
            float4 w = ((const float4*)wg)[lane + 32 * i];
            dg += v[i].x * w.x + v[i].y * w.y + v[i].z * w.z + v[i].w * w.w;
        }
    }
#pragma unroll
    for (int o = 16; o > 0; o >>= 1) {
        ss += __shfl_xor_sync(0xffffffffu, ss, o);
        dg += __shfl_xor_sync(0xffffffffu, dg, o);
    }
    const float inv = 1.f / fmaxf(sqrtf(ss), 1e-12f);
#pragma unroll
    for (int i = 0; i < 4; i++) {
        v[i].x *= inv; v[i].y *= inv; v[i].z *= inv; v[i].w *= inv;
        row[lane + 32 * i] = v[i];
    }
    if (wg && lane == 0) logit[gw] = dg * inv * ATTN_SCALE;
}

__global__ void softmax_stats_kernel(const float* __restrict__ logit,
                                     float* __restrict__ stats)
{
    const int b = blockIdx.x;
    const int tid = threadIdx.x;
    __shared__ float red[256];
    float mx = -1e30f;
    for (int n = tid; n < NT; n += 256) mx = fmaxf(mx, logit[b * NT + n]);
    red[tid] = mx; __syncthreads();
    for (int s = 128; s > 0; s >>= 1) {
        if (tid < s) red[tid] = fmaxf(red[tid], red[tid + s]);
        __syncthreads();
    }
    const float m = red[0]; __syncthreads();
    float se = 0.f;
    for (int n = tid; n < NT; n += 256) se += expf(logit[b * NT + n] - m);
    red[tid] = se; __syncthreads();
    for (int s = 128; s > 0; s >>= 1) {
        if (tid < s) red[tid] += red[tid + s];
        __syncthreads();
    }
    if (tid == 0) { stats[2 * b] = m; stats[2 * b + 1] = red[0]; }
}

__global__ void compute_g_kernel(const float* __restrict__ q,
                                 const float* __restrict__ logit,
                                 const float* __restrict__ stats,
                                 float* __restrict__ g)
{
    const int b = blockIdx.x;
    const int d = blockIdx.y * 128 + threadIdx.x;
    const float m = stats[2 * b];
    const float inv_s = 1.f / stats[2 * b + 1];
    __shared__ float w[128];
    float acc = 0.f;
    const float* qb = q + (long long)b * NT * D;
    for (int n0 = 0; n0 < NT; n0 += 128) {
        const int n = n0 + threadIdx.x;
        w[threadIdx.x] = (n < NT) ? expf(logit[b * NT + n] - m) * inv_s : 0.f;
        __syncthreads();
        const int lim = min(128, NT - n0);
        for (int j = 0; j < lim; j++)
            acc += w[j] * qb[(long long)(n0 + j) * D + d];
        __syncthreads();
    }
    g[b * D + d] = acc;
}

__global__ void scale_split_k_kernel(const float4* __restrict__ k,
                                     const float4* __restrict__ g,
                                     uint2* __restrict__ hi, uint2* __restrict__ lo)
{
    long long idx = (long long)blockIdx.x * blockDim.x + threadIdx.x;
    const long long total = (long long)M_K * (D / 4);
    if (idx >= total) return;
    const int c = (int)(idx & 127);
    const int b = (int)((idx >> 7) / NV);
    float4 kv = k[idx];
    const float4 gv = g[b * 128 + c];
    kv.x *= gv.x; kv.y *= gv.y; kv.z *= gv.z; kv.w *= gv.w;
    uint2 h, l;
    split4(kv, h, l);
    hi[idx] = h; lo[idx] = l;
}

// ---------------------------------------------------------------------------
// launch
// ---------------------------------------------------------------------------
extern "C" void kernel_launch(void* const* d_in, const int* in_sizes, int n_in,
                              void* d_out, int out_size)
{
    (void)in_sizes; (void)n_in; (void)out_size;

    const float* verts_f = (const float*)d_in[0];
    const float* img_f   = (const float*)d_in[1];
    const float* fc_w    = (const float*)d_in[2];
    const float* fc_b    = (const float*)d_in[3];
    const float* q_w     = (const float*)d_in[4];
    const float* q_b     = (const float*)d_in[5];
    const float* k_w     = (const float*)d_in[6];
    const float* k_b     = (const float*)d_in[7];
    const float* w_g     = (const float*)d_in[8];
    const float* proj_w  = (const float*)d_in[9];
    const float* proj_b  = (const float*)d_in[10];
    const float* final_w = (const float*)d_in[11];
    const float* final_b = (const float*)d_in[12];
    float* out = (float*)d_out;

    __half *xhi, *xlo, *ihi, *ilo, *gkhi, *gklo, *thi, *tlo, *whi;
    float *q, *k, *logit, *stats, *gq;
    cudaGetSymbolAddress((void**)&xhi,  g_xhi);
    cudaGetSymbolAddress((void**)&xlo,  g_xlo);
    cudaGetSymbolAddress((void**)&ihi,  g_ihi);
    cudaGetSymbolAddress((void**)&ilo,  g_ilo);
    cudaGetSymbolAddress((void**)&gkhi, g_gkhi);
    cudaGetSymbolAddress((void**)&gklo, g_gklo);
    cudaGetSymbolAddress((void**)&thi,  g_thi);
    cudaGetSymbolAddress((void**)&tlo,  g_tlo);
    cudaGetSymbolAddress((void**)&whi,  g_whi);
    cudaGetSymbolAddress((void**)&q,     g_q);
    cudaGetSymbolAddress((void**)&k,     g_k);
    cudaGetSymbolAddress((void**)&logit, g_logit);
    cudaGetSymbolAddress((void**)&stats, g_stats);
    cudaGetSymbolAddress((void**)&gq,    g_gq);

    cudaFuncSetAttribute(mma_gemm, cudaFuncAttributeMaxDynamicSharedMemorySize,
                         SMEM_GEMM);

    const long long sNT = (long long)NT * D;
    const long long ewT = (long long)M_K * (D / 4);
    const int ewB = (int)((ewT + 255) / 256);

    // --- input conversions ---
    {
        const long long n4 = W_TOTAL / 4;
        convert_w_kernel<<<(int)((n4 + 255) / 256), 256>>>(
            (const float4*)fc_w, (const float4*)q_w, (const float4*)k_w,
            (const float4*)proj_w, (const float4*)final_w, (uint2*)whi);
    }
    {
        const long long n4 = (long long)M_IMG * IMGD / 4;
        split_kernel<<<(int)((n4 + 255) / 256), 256>>>(
            (const float4*)img_f, (uint2*)ihi, (uint2*)ilo, n4);
    }
    split_verts_kernel<<<ewB, 256>>>((const float4*)verts_f,
                                     (uint2*)xhi, (uint2*)xlo);

    // x[:, NV:] = img_f @ fc_w^T + fc_b  (split output into x hi/lo)
    mma_gemm<<<dim3(M_IMG / 128, 4), 256, SMEM_GEMM>>>(
        ihi, ilo, IMGD, M_IMG, 0LL,
        whi + OFF_FC, fc_b,
        nullptr, 1, 0LL,
        nullptr, xhi + (long long)NV * D, xlo + (long long)NV * D,
        NI, sNT);

    // q = x @ q_w^T + q_b (all tokens, fp32 out)
    mma_gemm<<<dim3(M_Q / 128, 4), 256, SMEM_GEMM>>>(
        xhi, xlo, D, M_Q, 0LL,
        whi + OFF_QW, q_b,
        nullptr, 1, 0LL,
        q, nullptr, nullptr, M_Q, 0LL);
    l2norm_kernel<<<(M_Q * 32 + 255) / 256, 256>>>(q, M_Q, w_g, logit);

    // k = x_vert @ k_w^T + k_b (vertex tokens, fp32 out)
    mma_gemm<<<dim3(M_K / 128, 4), 256, SMEM_GEMM>>>(
        xhi, xlo, D, NV, sNT,
        whi + OFF_KW, k_b,
        nullptr, 1, 0LL,
        k, nullptr, nullptr, M_K, 0LL);
    l2norm_kernel<<<(M_K * 32 + 255) / 256, 256>>>(k, M_K, nullptr, nullptr);

    // softmax + global query
    softmax_stats_kernel<<<B, 256>>>(logit, stats);
    compute_g_kernel<<<dim3(B, 4), 128>>>(q, logit, stats, gq);

    // gk = g * k, split
    scale_split_k_kernel<<<ewB, 256>>>((const float4*)k, (const float4*)gq,
                                       (uint2*)gkhi, (uint2*)gklo);

    // t = gk @ proj_w^T + proj_b + q_vert (split output)
    mma_gemm<<<dim3(M_K / 128, 4), 256, SMEM_GEMM>>>(
        gkhi, gklo, D, M_K, 0LL,
        whi + OFF_PW, proj_b,
        q, NV, sNT,
        nullptr, thi, tlo, M_K, 0LL);

    // out = t @ final_w^T + final_b + verts_f (fp32 out)
    mma_gemm<<<dim3(M_K / 128, 4), 256, SMEM_GEMM>>>(
        thi, tlo, D, M_K, 0LL,
        whi + OFF_FW, final_b,
        verts_f, M_K, 0LL,
        out, nullptr, nullptr, M_K, 0LL);
}